// round 13
// baseline (speedup 1.0000x reference)
#include <cuda_runtime.h>
#include <math.h>
#include <stdint.h>

#define NUM_USERS 162541
#define NUM_ITEMS 59047
#define N_NODES   221588
#define DIM       128
#define N_EDGES   100000
#define BATCH     16384
#define MAXL1     132768
#define MAXL2     32768
#define NBLK      296        // persistent grid: 2 blocks/SM on 148 SMs
#define SA_STR    132        // sA stride (conflict-free mma A frags)
#define SB_STR    136        // sB stride (conflict-free mma B frags)

// ---------------- scratch (device globals; device-code use ONLY) ------------
__device__ float g_h1 [(size_t)N_NODES * DIM];   // h1; later h2
__device__ unsigned char g_need1[N_NODES], g_need2[N_NODES];
__device__ int g_list1[MAXL1], g_list2[MAXL2];
__device__ int g_cnt1, g_cnt2, g_tot1, g_tot2;
__device__ int g_deg1[N_NODES], g_deg2[N_NODES];
__device__ int g_base1[N_NODES], g_base2[N_NODES];
__device__ int g_fc1[N_NODES], g_fc2[N_NODES];
__device__ int g_csr1[N_EDGES], g_csr2[N_EDGES];
__device__ float g_ws1[4 * DIM], g_wd1[4 * DIM];
__device__ float g_ws2[DIM],     g_wd2[DIM];
__device__ unsigned g_gen, g_cntb;

// ---------------- helpers ---------------------------------------------------
__device__ __forceinline__ float eluf(float x)  { return x > 0.f ? x : expm1f(x); }
__device__ __forceinline__ float lrelu(float x) { return x > 0.f ? x : 0.2f * x; }
__device__ __forceinline__ float wsum(float v) {
    #pragma unroll
    for (int o = 16; o; o >>= 1) v += __shfl_xor_sync(0xffffffffu, v, o);
    return v;
}
__device__ __forceinline__ const float* xrow(int n, const float* uT, const float* iT) {
    return (n < NUM_USERS) ? uT + (size_t)n * DIM
                           : iT + (size_t)(n - NUM_USERS) * DIM;
}
__device__ __forceinline__ void mma8(float& c0, float& c1, float& c2, float& c3,
    uint32_t a0, uint32_t a1, uint32_t a2, uint32_t a3, uint32_t b0, uint32_t b1) {
    asm volatile("mma.sync.aligned.m16n8k8.row.col.f32.tf32.tf32.f32 "
        "{%0,%1,%2,%3}, {%4,%5,%6,%7}, {%8,%9}, {%0,%1,%2,%3};\n"
        : "+f"(c0), "+f"(c1), "+f"(c2), "+f"(c3)
        : "r"(a0), "r"(a1), "r"(a2), "r"(a3), "r"(b0), "r"(b1));
}
__device__ __forceinline__ void gridbar() {
    __syncthreads();
    if (threadIdx.x == 0) {
        __threadfence();
        unsigned gen = *((volatile unsigned*)&g_gen);
        if (atomicAdd(&g_cntb, 1) == NBLK - 1) {
            g_cntb = 0;
            __threadfence();
            atomicAdd(&g_gen, 1);
        } else {
            while (*((volatile unsigned*)&g_gen) == gen) { }
        }
        __threadfence();
    }
    __syncthreads();
}

// ---------------- 1: persistent graph-prep (5 phases, 1 launch) --------------
__global__ __launch_bounds__(256)
void megaprep_k(const float* __restrict__ W1, const float* __restrict__ aS1,
                const float* __restrict__ aD1, const float* __restrict__ W2,
                const float* __restrict__ aS2, const float* __restrict__ aD2,
                const int* __restrict__ uidx, const int* __restrict__ iidx,
                const int* __restrict__ ei)
{
    __shared__ int w1[8], w2[8];
    __shared__ int base1, base2;
    const int tid = threadIdx.x;
    const int gstride = NBLK * 256;

    if (blockIdx.x == 0) {
        if (tid == 128) { g_cnt1 = 0; g_cnt2 = 0; g_tot1 = 0; g_tot2 = 0; }
        if (tid < 128) {
            int k = tid;
            #pragma unroll
            for (int h = 0; h < 4; h++) {
                float s = 0.f, d = 0.f;
                #pragma unroll
                for (int c = 0; c < 32; c++) {
                    float w = W1[k * DIM + h * 32 + c];
                    s = fmaf(w, aS1[h * 32 + c], s);
                    d = fmaf(w, aD1[h * 32 + c], d);
                }
                g_ws1[h * DIM + k] = s;
                g_wd1[h * DIM + k] = d;
            }
            float s2 = 0.f, d2 = 0.f;
            for (int j = 0; j < DIM; j++) {
                float w = W2[k * DIM + j];
                s2 = fmaf(w, aS2[j], s2);
                d2 = fmaf(w, aD2[j], d2);
            }
            g_ws2[k] = s2;
            g_wd2[k] = d2;
        }
    }
    for (int i = blockIdx.x * 256 + tid; i < BATCH; i += gstride) {
        int u = uidx[i], v = iidx[i] + NUM_USERS;
        g_need2[u] = 1; g_need1[u] = 1;
        g_need2[v] = 1; g_need1[v] = 1;
    }
    gridbar();

    for (int e = blockIdx.x * 256 + tid; e < N_EDGES; e += gstride)
        if (g_need2[ei[N_EDGES + e]]) g_need1[ei[e]] = 1;
    gridbar();

    for (int e = blockIdx.x * 256 + tid; e < N_EDGES; e += gstride) {
        int d = ei[N_EDGES + e];
        if (g_need1[d]) atomicAdd(&g_deg1[d], 1);
        if (g_need2[d]) atomicAdd(&g_deg2[d], 1);
    }
    gridbar();

    for (int cb = blockIdx.x; cb * 256 < N_NODES; cb += NBLK) {
        int i = cb * 256 + tid;
        int w = tid >> 5, lane = tid & 31;
        bool in1 = (i < N_NODES) && g_need1[i];
        bool in2 = (i < N_NODES) && g_need2[i];
        unsigned m1 = __ballot_sync(~0u, in1);
        unsigned m2 = __ballot_sync(~0u, in2);
        if (lane == 0) { w1[w] = __popc(m1); w2[w] = __popc(m2); }
        __syncthreads();
        if (tid == 0) {
            int t1 = 0, t2 = 0;
            #pragma unroll
            for (int k = 0; k < 8; k++) {
                int v1 = w1[k]; w1[k] = t1; t1 += v1;
                int v2 = w2[k]; w2[k] = t2; t2 += v2;
            }
            base1 = (t1 > 0) ? atomicAdd(&g_cnt1, t1) : 0;
            base2 = (t2 > 0) ? atomicAdd(&g_cnt2, t2) : 0;
        }
        __syncthreads();
        unsigned lm = (1u << lane) - 1u;
        if (in1) g_list1[base1 + w1[w] + __popc(m1 & lm)] = i;
        if (in2) g_list2[base2 + w2[w] + __popc(m2 & lm)] = i;
        {
            int deg = in1 ? g_deg1[i] : 0;
            int inc = deg;
            #pragma unroll
            for (int o = 1; o < 32; o <<= 1) {
                int t = __shfl_up_sync(~0u, inc, o);
                if (lane >= o) inc += t;
            }
            int tot = __shfl_sync(~0u, inc, 31);
            int wb = 0;
            if (lane == 31 && tot > 0) wb = atomicAdd(&g_tot1, tot);
            wb = __shfl_sync(~0u, wb, 31);
            if (in1) g_base1[i] = wb + inc - deg;
        }
        {
            int deg = in2 ? g_deg2[i] : 0;
            int inc = deg;
            #pragma unroll
            for (int o = 1; o < 32; o <<= 1) {
                int t = __shfl_up_sync(~0u, inc, o);
                if (lane >= o) inc += t;
            }
            int tot = __shfl_sync(~0u, inc, 31);
            int wb = 0;
            if (lane == 31 && tot > 0) wb = atomicAdd(&g_tot2, tot);
            wb = __shfl_sync(~0u, wb, 31);
            if (in2) g_base2[i] = wb + inc - deg;
        }
        __syncthreads();
    }
    gridbar();

    for (int e = blockIdx.x * 256 + tid; e < N_EDGES; e += gstride) {
        int d = ei[N_EDGES + e], s = ei[e];
        if (g_need1[d]) g_csr1[g_base1[d] + atomicAdd(&g_fc1[d], 1)] = s;
        if (g_need2[d]) g_csr2[g_base2[d] + atomicAdd(&g_fc2[d], 1)] = s;
    }
}

// ---------------- 2: fused layer-1 gather + TF32-mma GEMM --------------------
// block = 16 need1 nodes (small tile -> 4 blocks/SM resident).
#define SM1_SA   (4 * 16 * SA_STR)
#define SM1_SB   (16 * SB_STR)
#define SMEM1    ((SM1_SA + SM1_SB + 1024) * 4 + 16 * 4)
__global__ __launch_bounds__(256, 4)
void fused1_k(const float* __restrict__ uT, const float* __restrict__ iT,
              const float* __restrict__ W1, const float* __restrict__ bias1)
{
    extern __shared__ float smem[];
    float* sA  = smem;                     // [h*16+slot][k], stride SA_STR
    float* sB  = sA + SM1_SA;
    float* sWs = sB + SM1_SB;              // [4][128]
    float* sWd = sWs + 512;
    int* sNode = (int*)(sWd + 512);

    const int cnt  = g_cnt1;
    const int row0 = blockIdx.x * 16;
    if (row0 >= cnt) return;
    const int tid  = threadIdx.x;
    const int w    = tid >> 5, lane = tid & 31;

    for (int i = tid; i < 512; i += 256) { sWs[i] = g_ws1[i]; sWd[i] = g_wd1[i]; }
    if (tid < 16) sNode[tid] = (row0 + tid < cnt) ? g_list1[row0 + tid] : -1;
    __syncthreads();

    // ---- gather: warp w -> slots 2w, 2w+1 ----
    for (int j2 = 0; j2 < 2; j2++) {
        int slot = w * 2 + j2;
        int d = sNode[slot];
        if (d < 0) {
            #pragma unroll
            for (int h = 0; h < 4; h++) {
                float* o = sA + (size_t)(h * 16 + slot) * SA_STR;
                o[lane] = 0.f; o[lane + 32] = 0.f; o[lane + 64] = 0.f; o[lane + 96] = 0.f;
            }
            continue;
        }
        const float* xd = xrow(d, uT, iT);
        float v0 = xd[lane], v1 = xd[lane + 32], v2 = xd[lane + 64], v3 = xd[lane + 96];
        float bd[4], den[4], acc[4][4];
        #pragma unroll
        for (int h = 0; h < 4; h++) {
            float ws0 = sWs[h * 128 + lane],      ws1 = sWs[h * 128 + lane + 32];
            float ws2 = sWs[h * 128 + lane + 64], ws3 = sWs[h * 128 + lane + 96];
            float wd0 = sWd[h * 128 + lane],      wd1 = sWd[h * 128 + lane + 32];
            float wd2 = sWd[h * 128 + lane + 64], wd3 = sWd[h * 128 + lane + 96];
            float ad = wsum(v0 * ws0 + v1 * ws1 + v2 * ws2 + v3 * ws3);
            bd[h]    = wsum(v0 * wd0 + v1 * wd1 + v2 * wd2 + v3 * wd3);
            float ww = expf(lrelu(ad + bd[h]));
            den[h] = ww;
            acc[h][0] = ww * v0; acc[h][1] = ww * v1;
            acc[h][2] = ww * v2; acc[h][3] = ww * v3;
        }
        int base = g_base1[d], deg = g_deg1[d];
        float e0 = 0.f, e1 = 0.f, e2 = 0.f, e3 = 0.f;
        if (deg > 0) {
            const float* xs = xrow(g_csr1[base], uT, iT);
            e0 = xs[lane]; e1 = xs[lane + 32]; e2 = xs[lane + 64]; e3 = xs[lane + 96];
        }
        for (int k = 0; k < deg; k++) {
            float c0 = e0, c1 = e1, c2 = e2, c3 = e3;
            if (k + 1 < deg) {        // prefetch next source row
                const float* xs = xrow(g_csr1[base + k + 1], uT, iT);
                e0 = xs[lane]; e1 = xs[lane + 32]; e2 = xs[lane + 64]; e3 = xs[lane + 96];
            }
            #pragma unroll
            for (int h = 0; h < 4; h++) {
                float as = wsum(c0 * sWs[h * 128 + lane] + c1 * sWs[h * 128 + lane + 32] +
                                c2 * sWs[h * 128 + lane + 64] + c3 * sWs[h * 128 + lane + 96]);
                float q = expf(lrelu(as + bd[h]));
                den[h] += q;
                acc[h][0] += q * c0; acc[h][1] += q * c1;
                acc[h][2] += q * c2; acc[h][3] += q * c3;
            }
        }
        #pragma unroll
        for (int h = 0; h < 4; h++) {
            float inv = 1.f / (den[h] + 1e-16f);
            float* o = sA + (size_t)(h * 16 + slot) * SA_STR;
            o[lane]      = acc[h][0] * inv;  o[lane + 32] = acc[h][1] * inv;
            o[lane + 64] = acc[h][2] * inv;  o[lane + 96] = acc[h][3] * inv;
        }
        if (lane == 0) { g_need1[d] = 0; g_deg1[d] = 0; g_fc1[d] = 0; }
    }
    __syncthreads();

    // ---- GEMM (tf32 mma): warp w -> head w>>1, n-half (w&1)*16 ----
    const int h  = w >> 1;
    const int nh = (w & 1) * 16;
    const int g  = lane >> 2;
    const int t  = lane & 3;
    float acc[2][4];
    #pragma unroll
    for (int i = 0; i < 2; i++)
        #pragma unroll
        for (int j = 0; j < 4; j++) acc[i][j] = 0.f;

    const int brow = tid >> 4;
    const int bcol = (tid & 15) * 8;
    const float* sAh = sA + (size_t)h * 16 * SA_STR;
    for (int kk = 0; kk < DIM; kk += 16) {
        *(float4*)&sB[brow * SB_STR + bcol]     = *(const float4*)(W1 + (size_t)(kk + brow) * DIM + bcol);
        *(float4*)&sB[brow * SB_STR + bcol + 4] = *(const float4*)(W1 + (size_t)(kk + brow) * DIM + bcol + 4);
        __syncthreads();
        #pragma unroll
        for (int k8 = 0; k8 < 16; k8 += 8) {
            uint32_t a0 = __float_as_uint(sAh[(g)     * SA_STR + kk + k8 + t]);
            uint32_t a1 = __float_as_uint(sAh[(g + 8) * SA_STR + kk + k8 + t]);
            uint32_t a2 = __float_as_uint(sAh[(g)     * SA_STR + kk + k8 + t + 4]);
            uint32_t a3 = __float_as_uint(sAh[(g + 8) * SA_STR + kk + k8 + t + 4]);
            #pragma unroll
            for (int nt = 0; nt < 2; nt++) {
                int n = h * 32 + nh + nt * 8 + g;
                uint32_t b0 = __float_as_uint(sB[(k8 + t)     * SB_STR + n]);
                uint32_t b1 = __float_as_uint(sB[(k8 + t + 4) * SB_STR + n]);
                mma8(acc[nt][0], acc[nt][1], acc[nt][2], acc[nt][3],
                     a0, a1, a2, a3, b0, b1);
            }
        }
        __syncthreads();
    }

    #pragma unroll
    for (int nt = 0; nt < 2; nt++) {
        int col = h * 32 + nh + nt * 8 + 2 * t;
        float b0 = bias1[col], b1 = bias1[col + 1];
        int s0 = g, s1 = g + 8;
        if (row0 + s0 < cnt) {
            float* o = g_h1 + (size_t)sNode[s0] * DIM + col;
            *(float2*)o = make_float2(eluf(acc[nt][0] + b0), eluf(acc[nt][1] + b1));
        }
        if (row0 + s1 < cnt) {
            float* o = g_h1 + (size_t)sNode[s1] * DIM + col;
            *(float2*)o = make_float2(eluf(acc[nt][2] + b0), eluf(acc[nt][3] + b1));
        }
    }
}

// ---------------- 3: fused layer-2 gather + TF32-mma GEMM --------------------
// block = 64 need2 nodes.
#define SM2_SA   (64 * SA_STR)
#define SM2_SB   (16 * SB_STR)
#define SMEM2    ((SM2_SA + SM2_SB + 256) * 4 + 64 * 4)
__global__ __launch_bounds__(256, 4)
void fused2_k(const float* __restrict__ W2, const float* __restrict__ bias2)
{
    extern __shared__ float smem[];
    float* sA  = smem;
    float* sB  = sA + SM2_SA;
    float* sWs = sB + SM2_SB;
    float* sWd = sWs + 128;
    int* sNode = (int*)(sWd + 128);

    const int cnt  = g_cnt2;
    const int row0 = blockIdx.x * 64;
    if (row0 >= cnt) return;
    const int tid  = threadIdx.x;
    const int w    = tid >> 5, lane = tid & 31;

    if (tid < 128) { sWs[tid] = g_ws2[tid]; sWd[tid] = g_wd2[tid]; }
    if (tid < 64) sNode[tid] = (row0 + tid < cnt) ? g_list2[row0 + tid] : -1;
    __syncthreads();

    // ---- gather: warp w -> slots w*8 .. w*8+7 ----
    for (int j8 = 0; j8 < 8; j8++) {
        int slot = w * 8 + j8;
        int d = sNode[slot];
        float* o = sA + (size_t)slot * SA_STR;
        if (d < 0) {
            o[lane] = 0.f; o[lane + 32] = 0.f; o[lane + 64] = 0.f; o[lane + 96] = 0.f;
            continue;
        }
        float wr0 = sWs[lane],      wr1 = sWs[lane + 32];
        float wr2 = sWs[lane + 64], wr3 = sWs[lane + 96];
        const float* hd = g_h1 + (size_t)d * DIM;
        float v0 = hd[lane], v1 = hd[lane + 32], v2 = hd[lane + 64], v3 = hd[lane + 96];
        float ad  = wsum(v0 * wr0 + v1 * wr1 + v2 * wr2 + v3 * wr3);
        float b2d = wsum(v0 * sWd[lane] + v1 * sWd[lane + 32] +
                         v2 * sWd[lane + 64] + v3 * sWd[lane + 96]);
        float ww = expf(lrelu(ad + b2d));
        float den = ww;
        float a0 = ww * v0, a1 = ww * v1, a2 = ww * v2, a3 = ww * v3;
        int base = g_base2[d], deg = g_deg2[d];
        float e0 = 0.f, e1 = 0.f, e2 = 0.f, e3 = 0.f;
        if (deg > 0) {
            const float* hs = g_h1 + (size_t)g_csr2[base] * DIM;
            e0 = hs[lane]; e1 = hs[lane + 32]; e2 = hs[lane + 64]; e3 = hs[lane + 96];
        }
        for (int k = 0; k < deg; k++) {
            float c0 = e0, c1 = e1, c2 = e2, c3 = e3;
            if (k + 1 < deg) {        // prefetch next source row
                const float* hs = g_h1 + (size_t)g_csr2[base + k + 1] * DIM;
                e0 = hs[lane]; e1 = hs[lane + 32]; e2 = hs[lane + 64]; e3 = hs[lane + 96];
            }
            float as = wsum(c0 * wr0 + c1 * wr1 + c2 * wr2 + c3 * wr3);
            float q = expf(lrelu(as + b2d));
            den += q;
            a0 += q * c0; a1 += q * c1; a2 += q * c2; a3 += q * c3;
        }
        float inv = 1.f / (den + 1e-16f);
        o[lane]      = a0 * inv;  o[lane + 32] = a1 * inv;
        o[lane + 64] = a2 * inv;  o[lane + 96] = a3 * inv;
        if (lane == 0) { g_need2[d] = 0; g_deg2[d] = 0; g_fc2[d] = 0; }
    }
    __syncthreads();

    // ---- GEMM (tf32 mma): warp w -> m-tile (w>>1), n-half (w&1)*64 ----
    const int g  = lane >> 2;
    const int t  = lane & 3;
    const int mt = (w >> 1) * 16;
    const int nh = (w & 1) * 64;
    float acc[8][4];
    #pragma unroll
    for (int i = 0; i < 8; i++)
        #pragma unroll
        for (int j = 0; j < 4; j++) acc[i][j] = 0.f;

    const int brow = tid >> 4;
    const int bcol = (tid & 15) * 8;
    for (int kk = 0; kk < DIM; kk += 16) {
        *(float4*)&sB[brow * SB_STR + bcol]     = *(const float4*)(W2 + (size_t)(kk + brow) * DIM + bcol);
        *(float4*)&sB[brow * SB_STR + bcol + 4] = *(const float4*)(W2 + (size_t)(kk + brow) * DIM + bcol + 4);
        __syncthreads();
        #pragma unroll
        for (int k8 = 0; k8 < 16; k8 += 8) {
            uint32_t a0 = __float_as_uint(sA[(mt + g)     * SA_STR + kk + k8 + t]);
            uint32_t a1 = __float_as_uint(sA[(mt + g + 8) * SA_STR + kk + k8 + t]);
            uint32_t a2 = __float_as_uint(sA[(mt + g)     * SA_STR + kk + k8 + t + 4]);
            uint32_t a3 = __float_as_uint(sA[(mt + g + 8) * SA_STR + kk + k8 + t + 4]);
            #pragma unroll
            for (int nt = 0; nt < 8; nt++) {
                int n = nh + nt * 8 + g;
                uint32_t b0 = __float_as_uint(sB[(k8 + t)     * SB_STR + n]);
                uint32_t b1 = __float_as_uint(sB[(k8 + t + 4) * SB_STR + n]);
                mma8(acc[nt][0], acc[nt][1], acc[nt][2], acc[nt][3],
                     a0, a1, a2, a3, b0, b1);
            }
        }
        __syncthreads();
    }

    #pragma unroll
    for (int nt = 0; nt < 8; nt++) {
        int col = nh + nt * 8 + 2 * t;
        float b0 = bias2[col], b1 = bias2[col + 1];
        int s0 = mt + g, s1 = mt + g + 8;
        if (row0 + s0 < cnt) {
            float* o = g_h1 + (size_t)sNode[s0] * DIM + col;   // h2 aliases h1
            *(float2*)o = make_float2(eluf(acc[nt][0] + b0), eluf(acc[nt][1] + b1));
        }
        if (row0 + s1 < cnt) {
            float* o = g_h1 + (size_t)sNode[s1] * DIM + col;
            *(float2*)o = make_float2(eluf(acc[nt][2] + b0), eluf(acc[nt][3] + b1));
        }
    }
}

// ---------------- 4: final dot + sigmoid -------------------------------------
__global__ __launch_bounds__(256)
void final_k(const int* __restrict__ uidx, const int* __restrict__ iidx,
             float* __restrict__ res)
{
    int b    = (blockIdx.x * blockDim.x + threadIdx.x) >> 5;
    int lane = threadIdx.x & 31;
    if (b >= BATCH) return;
    const float* ru = g_h1 + (size_t)uidx[b] * DIM;
    const float* rv = g_h1 + (size_t)(iidx[b] + NUM_USERS) * DIM;
    float dot = ru[lane]      * rv[lane]
              + ru[lane + 32] * rv[lane + 32]
              + ru[lane + 64] * rv[lane + 64]
              + ru[lane + 96] * rv[lane + 96];
    dot = wsum(dot);
    if (lane == 0) res[b] = 1.f / (1.f + expf(-dot));
}

// ---------------- launch -----------------------------------------------------
extern "C" void kernel_launch(void* const* d_in, const int* in_sizes, int n_in,
                              void* d_out, int out_size)
{
    const int*   uidx  = (const int*)  d_in[0];
    const int*   iidx  = (const int*)  d_in[1];
    const int*   ei    = (const int*)  d_in[2];
    const float* userT = (const float*)d_in[3];
    const float* itemT = (const float*)d_in[4];
    const float* W1    = (const float*)d_in[5];
    const float* attS1 = (const float*)d_in[6];
    const float* attD1 = (const float*)d_in[7];
    const float* bias1 = (const float*)d_in[8];
    const float* W2    = (const float*)d_in[9];
    const float* attS2 = (const float*)d_in[10];
    const float* attD2 = (const float*)d_in[11];
    const float* bias2 = (const float*)d_in[12];
    float* res = (float*)d_out;

    cudaFuncSetAttribute(fused1_k, cudaFuncAttributeMaxDynamicSharedMemorySize, SMEM1);
    cudaFuncSetAttribute(fused2_k, cudaFuncAttributeMaxDynamicSharedMemorySize, SMEM2);

    megaprep_k<<<NBLK, 256>>>(W1, attS1, attD1, W2, attS2, attD2, uidx, iidx, ei);
    fused1_k  <<<(MAXL1 + 15) / 16, 256, SMEM1>>>(userT, itemT, W1, bias1);
    fused2_k  <<<(MAXL2 + 63) / 64, 256, SMEM2>>>(W2, bias2);
    final_k   <<<(BATCH + 7) / 8, 256>>>(uidx, iidx, res);
}